// round 14
// baseline (speedup 1.0000x reference)
#include <cuda_runtime.h>
#include <math.h>
#include <stdint.h>

#define B_ 64
#define C_ 3
#define N_ 512
#define TILE_Y 4
#define HALO (TILE_Y + 2)                  // 6 rows incl. halo
#define CH_F (HALO * N_)                   // floats per channel buffer (3072)
#define BUF_F (C_ * CH_F)                  // floats per buffer (9216)
#define SMEM_BYTES (2 * BUF_F * 4)         // 73728
#define NTILES (B_ * (N_ / TILE_Y))        // 8192
#define GRID_CTAS 444                      // 148 SMs * 3 CTAs

__device__ __forceinline__ uint32_t smem_u32(const void* p) {
    uint32_t a;
    asm("{ .reg .u64 t; cvta.to.shared.u64 t, %1; cvt.u32.u64 %0, t; }"
        : "=r"(a) : "l"(p));
    return a;
}

__device__ __forceinline__ void mbar_wait(uint32_t mb, uint32_t parity) {
    uint32_t done;
    asm volatile(
        "{\n .reg .pred p;\n"
        " mbarrier.try_wait.parity.acquire.cta.shared::cta.b64 p, [%1], %2;\n"
        " selp.b32 %0, 1, 0, p;\n}"
        : "=r"(done) : "r"(mb), "r"(parity) : "memory");
    while (!done) {
        asm volatile(
            "{\n .reg .pred p;\n"
            " mbarrier.try_wait.parity.acquire.cta.shared::cta.b64 p, [%1], %2, 0x989680;\n"
            " selp.b32 %0, 1, 0, p;\n}"
            : "=r"(done) : "r"(mb), "r"(parity) : "memory");
    }
}

__global__ void __launch_bounds__(256)
diffeo_kernel(const float* __restrict__ x,
              const float* __restrict__ Fx,
              const float* __restrict__ Fy,
              float* __restrict__ out,
              float scale) {
    extern __shared__ float S[];                        // [2][3][HALO][512]
    __shared__ __align__(8) unsigned long long mbars[2];

    // envelope e[i][j] = 1/sqrt((i+1)^2+(j+1)^2), zeroed where r >= 4.5
    constexpr float ENV[16] = {
        0.7071067812f, 0.4472135955f, 0.3162277660f, 0.2425356250f,
        0.4472135955f, 0.3535533906f, 0.2773500981f, 0.2236067977f,
        0.3162277660f, 0.2773500981f, 0.2357022604f, 0.0f,
        0.2425356250f, 0.2236067977f, 0.0f,          0.0f
    };

    const int tid   = threadIdx.x;
    const int warp  = tid >> 5;
    const int lane  = tid & 31;
    const int wrow  = warp >> 1;                       // row within tile (0..3)
    const int xhalf = (warp & 1) * 256;                // column half

    const uint32_t mb0 = smem_u32(&mbars[0]);
    const uint32_t mb1 = smem_u32(&mbars[1]);

    if (tid == 0) {
        asm volatile("mbarrier.init.shared.b64 [%0], %1;" :: "r"(mb0), "r"(1u) : "memory");
        asm volatile("mbarrier.init.shared.b64 [%0], %1;" :: "r"(mb1), "r"(1u) : "memory");
    }
    __syncthreads();

    // --- copy issuer: 3 contiguous bulk copies for tile t into buffer buf ---
    auto issue_load = [&](int t, int buf) {
        const int b    = t >> 7;                       // t / 128
        const int y0   = (t & 127) * TILE_Y;
        int gy0 = y0 - 1, lr0 = 0;
        if (gy0 < 0) { gy0 = 0; lr0 = 1; }
        int gy1 = y0 + TILE_Y;
        if (gy1 > N_ - 1) gy1 = N_ - 1;
        const unsigned rbytes = (unsigned)(gy1 - gy0 + 1) * N_ * 4u;
        const uint32_t mb = buf ? mb1 : mb0;

        asm volatile("mbarrier.arrive.expect_tx.shared.b64 _, [%0], %1;"
                     :: "r"(mb), "r"(rbytes * 3u) : "memory");
#pragma unroll
        for (int c = 0; c < C_; c++) {
            const float* src = x + ((size_t)(b * C_ + c) * N_ + gy0) * N_;
            const uint32_t dst = smem_u32(S + buf * BUF_F + c * CH_F + lr0 * N_);
            asm volatile(
                "cp.async.bulk.shared::cta.global.mbarrier::complete_tx::bytes "
                "[%0], [%1], %2, [%3];"
                :: "r"(dst), "l"(src), "r"(rbytes), "r"(mb) : "memory");
        }
    };

    const float PI_INV = (float)M_PI / (float)(N_ - 1);
    const float stepA  = 32.0f * PI_INV;
    const float sd = __sinf(stepA), cd = __cosf(stepA);
    const float HIX = __uint_as_float(0x43FF7FFFu);    // 510.99997

    // prologue: load first tile into buffer 0
    const int t0 = blockIdx.x;
    if (tid == 0 && t0 < NTILES) issue_load(t0, 0);

    uint32_t phase0 = 0, phase1 = 0;
    int i = 0;
    for (int t = t0; t < NTILES; t += GRID_CTAS, i++) {
        const int cur = i & 1;

        // buffer cur^1 is free once ALL warps finished tile i-1
        __syncthreads();
        if (tid == 0 && t + GRID_CTAS < NTILES) issue_load(t + GRID_CTAS, cur ^ 1);

        const int b  = t >> 7;
        const int y0 = (t & 127) * TILE_Y;
        const int y  = y0 + wrow;

        // ---- per-warp row coefficients (overlaps the in-flight copy) ----
        const float py = (float)y * PI_INV;
        const float sy0 = __sinf(py), sy1 = __sinf(py * 2.0f);
        const float sy2 = __sinf(py * 3.0f), sy3 = __sinf(py * 4.0f);

        float gu[4], gv[4];
#pragma unroll
        for (int q = 0; q < 4; q++) {
            float4 fx  = __ldg((const float4*)(Fx + b * 16 + q * 4));
            float4 fy4 = __ldg((const float4*)(Fy + b * 16 + q * 4));
            gu[q] = fmaf(fx.x * ENV[q*4+0], sy0, fmaf(fx.y * ENV[q*4+1], sy1,
                    fmaf(fx.z * ENV[q*4+2], sy2,      fx.w * ENV[q*4+3] * sy3)));
            gv[q] = fmaf(fy4.x * ENV[q*4+0], sy0, fmaf(fy4.y * ENV[q*4+1], sy1,
                    fmaf(fy4.z * ENV[q*4+2], sy2,     fy4.w * ENV[q*4+3] * sy3)));
        }

        float s1 = __sinf((float)(xhalf + lane) * PI_INV);
        float c1 = __cosf((float)(xhalf + lane) * PI_INV);

        const float fy = (float)y;
        const float LOY = (y0 > 0) ? (float)(y0 - 1) : 0.0f;
        const float HIY = fminf(HIX, (float)(y0 + TILE_Y) - 0.001f);
        const float ybase = (float)(y0 - 1);

        // wait for this tile's data
        if (cur) { mbar_wait(mb1, phase1); phase1 ^= 1; }
        else     { mbar_wait(mb0, phase0); phase0 ^= 1; }

        const float* Sb = S + cur * BUF_F;
        float* orow = out + (size_t)(b * C_) * (N_ * N_) + y * N_;

#pragma unroll
        for (int it = 0; it < 8; it++) {
            const int xi = xhalf + it * 32 + lane;

            const float s2 = 2.0f * s1 * c1;
            const float c2 = fmaf(2.0f * c1, c1, -1.0f);
            const float s3 = fmaf(s1, c2, c1 * s2);
            const float s4 = 2.0f * s2 * c2;

            const float u = fmaf(gu[0], s1, fmaf(gu[1], s2, fmaf(gu[2], s3, gu[3] * s4)));
            const float v = fmaf(gv[0], s1, fmaf(gv[1], s2, fmaf(gv[2], s3, gv[3] * s4)));

            const float xn = fminf(fmaxf((float)xi - scale * u, 0.0f), HIX);
            const float yn = fminf(fmaxf(fy        - scale * v, LOY), HIY);

            const float xff = floorf(xn);
            const float yff = floorf(yn);
            const int   xf  = (int)xff;
            const float xv  = xn - xff;
            const float yv  = yn - yff;
            const int   r   = (int)(yff - ybase);      // local halo row 0..5

            const float w00 = (1.0f - yv) * (1.0f - xv);
            const float w01 = (1.0f - yv) * xv;
            const float w10 = yv * (1.0f - xv);
            const float w11 = yv * xv;

            const float* base = Sb + r * N_ + xf;      // taps: imm offsets

            float tv[12];
#pragma unroll
            for (int c = 0; c < C_; c++) {
                const int off = c * CH_F;
                tv[c*4+0] = base[off];
                tv[c*4+1] = base[off + 1];
                tv[c*4+2] = base[off + N_];
                tv[c*4+3] = base[off + N_ + 1];
            }

            const float ns = fmaf(s1, cd,  c1 * sd);
            const float nc = fmaf(c1, cd, -s1 * sd);
            s1 = ns; c1 = nc;

#pragma unroll
            for (int c = 0; c < C_; c++) {
                float val = fmaf(w00, tv[c*4+0], fmaf(w01, tv[c*4+1],
                            fmaf(w10, tv[c*4+2],      w11 * tv[c*4+3])));
                __stcs(&orow[c * (N_ * N_) + xi], val);
            }
        }
    }
}

extern "C" void kernel_launch(void* const* d_in, const int* in_sizes, int n_in,
                              void* d_out, int out_size) {
    const float* x  = (const float*)d_in[0];
    const float* Fx = (const float*)d_in[1];
    const float* Fy = (const float*)d_in[2];
    float* out = (float*)d_out;

    const double n_d  = (double)N_;
    const double typ  = n_d * sqrt(M_PI * log(4.0)) / 2.0;
    const double T    = 0.01;
    const float scale = (float)(sqrt(T / (typ * typ)) * n_d);

    cudaFuncSetAttribute(diffeo_kernel,
                         cudaFuncAttributeMaxDynamicSharedMemorySize, SMEM_BYTES);

    dim3 block(256);
    dim3 grid(GRID_CTAS);
    diffeo_kernel<<<grid, block, SMEM_BYTES>>>(x, Fx, Fy, out, scale);
}